// round 12
// baseline (speedup 1.0000x reference)
#include <cuda_runtime.h>
#include <math.h>

#define B   128
#define NZ  128
#define H   512
#define V   8192
#define S   64
#define H3  1536
#define EPS_BN  1e-5f
#define EPS_COS 1e-8f
#define NEG 0.2f
#define BV  (B*V)

// ---------------- static device scratch (allocations forbidden) ------------
__device__ __align__(16) float d_z0 [B*H];
__device__ __align__(16) float d_siz[B*H];
__device__ __align__(16) float d_cz [B*H3];
__device__ __align__(16) float d_gim[S*H3];
__device__ float d_g[(size_t)S*BV];           // 256 MiB gumbel noise
__device__ __align__(16) float d_six[B*H];
__device__ __align__(16) float d_gi [B*H3];
__device__ __align__(16) float d_ghx[B*H3];
__device__ __align__(16) float d_ghm[B*H3];
__device__ __align__(16) float d_hx [B*H];
__device__ __align__(16) float d_hm [B*H];
__device__ __align__(16) float d_o  [B*H];
__device__ float d_logits[B*V];
__device__ int   d_prev[B];
__device__ unsigned d_keys[2*S];

// ---------------- threefry2x32 (bit-exact vs JAX) --------------------------
__device__ __forceinline__ void threefry(unsigned k0, unsigned k1,
                                         unsigned c0, unsigned c1,
                                         unsigned &o0, unsigned &o1) {
  unsigned ks2 = k0 ^ k1 ^ 0x1BD11BDAu;
  unsigned x0 = c0 + k0, x1 = c1 + k1;
#define TFR(r) { x0 += x1; x1 = (x1 << (r)) | (x1 >> (32 - (r))); x1 ^= x0; }
  TFR(13) TFR(15) TFR(26) TFR(6)   x0 += k1;  x1 += ks2 + 1u;
  TFR(17) TFR(29) TFR(16) TFR(24)  x0 += ks2; x1 += k0 + 2u;
  TFR(13) TFR(15) TFR(26) TFR(6)   x0 += k0;  x1 += k1 + 3u;
  TFR(17) TFR(29) TFR(16) TFR(24)  x0 += k1;  x1 += ks2 + 4u;
  TFR(13) TFR(15) TFR(26) TFR(6)   x0 += ks2; x1 += k0 + 5u;
#undef TFR
  o0 = x0; o1 = x1;
}

__device__ __forceinline__ float gumbel_from_bits(unsigned bits) {
  float f = __uint_as_float((bits >> 9) | 0x3f800000u) - 1.0f;   // [0,1)
  float u = fmaxf(1e-6f, __fadd_rn(__fmul_rn(f, (1.0f - 1e-6f) - 1e-6f), 1e-6f));
  return -logf(-logf(u));
}

__global__ void k_keys() {
  int s = threadIdx.x;
  if (s < S) { unsigned o0,o1; threefry(0u,42u,0u,(unsigned)s,o0,o1);
               d_keys[2*s]=o0; d_keys[2*s+1]=o1; }
}

// Partitionable threefry random_bits: counter (0, i), 32-bit out = o0 ^ o1.
__global__ void k_gumbel() {
  int idx = blockIdx.x * blockDim.x + threadIdx.x;
  int s = idx / BV;
  int i = idx - s * BV;
  unsigned o0,o1;
  threefry(d_keys[2*s], d_keys[2*s+1], 0u, (unsigned)i, o0, o1);
  d_g[(size_t)s * BV + i] = gumbel_from_bits(o0 ^ o1);
}

// ---------------- helpers ---------------------------------------------------
__device__ __forceinline__ float bredsum(float v, float* sh) {
  int t = threadIdx.x;
  sh[t] = v; __syncthreads();
#pragma unroll
  for (int o = 64; o > 0; o >>= 1) { if (t < o) sh[t] += sh[t+o]; __syncthreads(); }
  float r = sh[0]; __syncthreads();
  return r;
}
__device__ __forceinline__ float leaky(float x) { return x >= 0.f ? x : NEG*x; }
__device__ __forceinline__ float sig(float x)   { return 1.f/(1.f+expf(-x)); }

// ---------------- setup kernels ---------------------------------------------
__global__ void k_z0(const float* __restrict__ z, const float* __restrict__ w,
                     const float* __restrict__ bias, const float* __restrict__ gg,
                     const float* __restrict__ bb) {
  __shared__ float sh[128];
  int b = threadIdx.x, c0 = blockIdx.x * 4;
  const float* zr = z + b*NZ;
  for (int j = 0; j < 4; j++) {
    int col = c0 + j;
    float acc = bias[col];
    const float* wr = w + col*NZ;
    for (int k = 0; k < NZ; k++) acc = fmaf(zr[k], wr[k], acc);
    float v   = leaky(acc);
    float mu  = bredsum(v, sh) * (1.f/B);
    float dd  = v - mu;
    float var = bredsum(dd*dd, sh) * (1.f/B);
    d_z0[b*H + col] = gg[col]*dd*rsqrtf(var + EPS_BN) + bb[col];
  }
}

__global__ void k_prep() {
  int i = blockIdx.x * blockDim.x + threadIdx.x;
  if (i < B*H) { float v = d_z0[i]; d_hx[i] = v; d_hm[i] = v; }
  if (i < B) d_prev[i] = V - 1;
}

__global__ void k_siz(const float* __restrict__ g2, const float* __restrict__ b2) {
  __shared__ float sh[128];
  int b = threadIdx.x, c0 = blockIdx.x * 4;
  for (int j = 0; j < 4; j++) {
    int col = c0 + j;
    float v   = d_z0[b*H + col];
    float mu  = bredsum(v, sh) * (1.f/B);
    float dd  = v - mu;
    float var = bredsum(dd*dd, sh) * (1.f/B);
    d_siz[b*H + col] = g2[H+col]*dd*rsqrtf(var + EPS_BN) + b2[H+col];
  }
}

__global__ void k_gim(const float* __restrict__ mem, const float* __restrict__ W,
                      const float* __restrict__ bias) {
  __shared__ float a[2*H];
  int s = blockIdx.x;
  for (int k = threadIdx.x; k < 2*H; k += 256) a[k] = mem[(size_t)s*2*H + k];
  __syncthreads();
  for (int n = threadIdx.x; n < H3; n += 256) {
    float acc = bias[n];
    const float* w = W + (size_t)n*2*H;
    for (int k = 0; k < 2*H; k++) acc = fmaf(a[k], w[k], acc);
    d_gim[s*H3 + n] = acc;
  }
}

__global__ void k_embbn(const float* __restrict__ emb,
                        const float* __restrict__ g2, const float* __restrict__ b2) {
  __shared__ float sh[128];
  int b = threadIdx.x, c0 = blockIdx.x * 4;
  const float* er = emb + (size_t)d_prev[b]*H;
  for (int j = 0; j < 4; j++) {
    int col = c0 + j;
    float e   = leaky(er[col]);
    float mu  = bredsum(e, sh) * (1.f/B);
    float dd  = e - mu;
    float var = bredsum(dd*dd, sh) * (1.f/B);
    d_six[b*H + col] = g2[col]*dd*rsqrtf(var + EPS_BN) + b2[col];
  }
}

// ---------------- tiled fp32 GEMM core, K-chunk 32 + register prefetch ------
// C[128, n0:n0+8*RPT] = A[128,512] @ W^T (+bias)(+addM)((+g)/t)
// 256 threads; per-thread RPT rows x 4 cols. Same FMA order as R5 (bit-exact).
template <int RPT>
__device__ __forceinline__ void gemm_core(
    const float* __restrict__ A, const float* __restrict__ W, int ldw,
    const float* __restrict__ bias, const float* __restrict__ addM, int ldadd,
    float* __restrict__ C, int ldc, int n0,
    const float* __restrict__ gbase, float t) {
  constexpr int NT = 8 * RPT;
  constexpr int TX = NT / 4;
  constexpr int WF = (NT * 8) / 256;   // W float4 loads/thread/chunk (1 or 2)
  __shared__ __align__(16) float Ash[32][132];
  __shared__ __align__(16) float Wsh[32][NT + 4];
  int tid = threadIdx.x;
  int tx = tid % TX, ty = tid / TX;
  int r0 = ty * RPT, c0 = tx * 4;
  float acc[RPT][4];
#pragma unroll
  for (int j = 0; j < RPT; j++)
#pragma unroll
    for (int c = 0; c < 4; c++) acc[j][c] = 0.f;

  float4 aR[4], wR[WF];
  // prefetch chunk 0 into registers
#pragma unroll
  for (int i = 0; i < 4; i++) {
    int e = tid + i*256; int row = e >> 3, kq = e & 7;
    aR[i] = *(const float4*)(A + row*512 + kq*4);
  }
#pragma unroll
  for (int i = 0; i < WF; i++) {
    int e = tid + i*256; int wr = e >> 3, kq = e & 7;
    wR[i] = *(const float4*)(W + (size_t)(n0+wr)*ldw + kq*4);
  }

  for (int it = 0; it < 16; it++) {
    // store staged chunk (A transposed to [k][row], W to [k][col])
#pragma unroll
    for (int i = 0; i < 4; i++) {
      int e = tid + i*256; int row = e >> 3, kq = e & 7;
      Ash[kq*4+0][row] = aR[i].x; Ash[kq*4+1][row] = aR[i].y;
      Ash[kq*4+2][row] = aR[i].z; Ash[kq*4+3][row] = aR[i].w;
    }
#pragma unroll
    for (int i = 0; i < WF; i++) {
      int e = tid + i*256; int wr = e >> 3, kq = e & 7;
      Wsh[kq*4+0][wr] = wR[i].x; Wsh[kq*4+1][wr] = wR[i].y;
      Wsh[kq*4+2][wr] = wR[i].z; Wsh[kq*4+3][wr] = wR[i].w;
    }
    __syncthreads();
    // prefetch next chunk; LDG latency hides behind the 32-k FMA burst
    if (it < 15) {
      int kt = (it+1) * 32;
#pragma unroll
      for (int i = 0; i < 4; i++) {
        int e = tid + i*256; int row = e >> 3, kq = e & 7;
        aR[i] = *(const float4*)(A + row*512 + kt + kq*4);
      }
#pragma unroll
      for (int i = 0; i < WF; i++) {
        int e = tid + i*256; int wr = e >> 3, kq = e & 7;
        wR[i] = *(const float4*)(W + (size_t)(n0+wr)*ldw + kt + kq*4);
      }
    }
#pragma unroll
    for (int kk = 0; kk < 32; kk++) {
      float av[RPT];
#pragma unroll
      for (int q = 0; q < RPT/4; q++) {
        float4 aa = *(const float4*)&Ash[kk][r0 + q*4];
        av[q*4+0]=aa.x; av[q*4+1]=aa.y; av[q*4+2]=aa.z; av[q*4+3]=aa.w;
      }
      float4 ww = *(const float4*)&Wsh[kk][c0];
      float wv4[4] = {ww.x, ww.y, ww.z, ww.w};
#pragma unroll
      for (int j = 0; j < RPT; j++)
#pragma unroll
        for (int c = 0; c < 4; c++)
          acc[j][c] = fmaf(av[j], wv4[c], acc[j][c]);
    }
    __syncthreads();
  }
#pragma unroll
  for (int j = 0; j < RPT; j++) {
    int row = r0 + j;
#pragma unroll
    for (int c = 0; c < 4; c++) {
      int col = n0 + c0 + c;
      float v = acc[j][c];
      if (bias)  v += bias[col];
      if (addM)  v += addM[(size_t)row*ldadd + col];
      if (gbase) v = (v + gbase[(size_t)row*V + col]) / t;
      C[(size_t)row*ldc + col] = v;
    }
  }
}

__global__ void __launch_bounds__(256) k_cz(const float* __restrict__ W,
                                            const float* __restrict__ bias) {
  gemm_core<4>(d_siz, W + H, 2*H, bias, (const float*)0, 0,
               d_cz, H3, blockIdx.x*32, (const float*)0, 1.f);
}

__global__ void __launch_bounds__(256) k_gemm3(
    const float* __restrict__ wih_x, const float* __restrict__ whh_x,
    const float* __restrict__ whh_m, const float* __restrict__ bhh_x,
    const float* __restrict__ bhh_m) {
  int n0 = blockIdx.x * 32;
  int z = blockIdx.z;
  const float* A    = (z==0) ? d_six : (z==1) ? d_hx : d_hm;
  const float* W    = (z==0) ? wih_x : (z==1) ? whh_x : whh_m;
  int ldw           = (z==0) ? 2*H : H;
  const float* bias = (z==0) ? (const float*)0 : (z==1) ? bhh_x : bhh_m;
  const float* addM = (z==0) ? d_cz : (const float*)0;
  float* Cm         = (z==0) ? d_gi : (z==1) ? d_ghx : d_ghm;
  gemm_core<4>(A, W, ldw, bias, addM, H3, Cm, H3, n0, (const float*)0, 1.f);
}

// 256 blocks x N-tile 32: 2 blocks/SM -> 16 warps/SM for latency hiding.
__global__ void __launch_bounds__(256) k_logits(
    int s, const float* __restrict__ W, const float* __restrict__ bias,
    const float* __restrict__ tptr) {
  gemm_core<4>(d_o, W, H, bias, (const float*)0, 0, d_logits, V,
               blockIdx.x*32, d_g + (size_t)s*BV, *tptr);
}

// ---------------- per-step: GRU combine + cosine gate + bn3 ------------------
__global__ void k_gru(int s, const float* __restrict__ g3, const float* __restrict__ b3) {
  __shared__ float sh[128];
  int b = threadIdx.x, c0 = blockIdx.x * 4;
  const float* gim = d_gim + s*H3;
  float hx2[4], hm2[4];
#pragma unroll
  for (int j = 0; j < 4; j++) {
    int col = c0 + j;
    float ir = d_gi [b*H3+col], iz = d_gi [b*H3+H+col], in_ = d_gi [b*H3+2*H+col];
    float hr = d_ghx[b*H3+col], hz = d_ghx[b*H3+H+col], hn  = d_ghx[b*H3+2*H+col];
    float h  = d_hx[b*H+col];
    float r  = sig(ir+hr), zg = sig(iz+hz);
    float n  = tanhf(in_ + r*hn);
    hx2[j] = (1.f-zg)*n + zg*h;
    float mir = gim[col], miz = gim[H+col], min_ = gim[2*H+col];
    float mhr = d_ghm[b*H3+col], mhz = d_ghm[b*H3+H+col], mhn = d_ghm[b*H3+2*H+col];
    float hmv = d_hm[b*H+col];
    float rm  = sig(mir+mhr), zm = sig(miz+mhz);
    float nm  = tanhf(min_ + rm*mhn);
    hm2[j] = (1.f-zm)*nm + zm*hmv;
    d_hx[b*H+col] = hx2[j];
    d_hm[b*H+col] = hm2[j];
  }
  float dot=0.f, na=0.f, nb=0.f;
#pragma unroll
  for (int j = 0; j < 4; j++) { dot += hx2[j]*hm2[j]; na += hx2[j]*hx2[j]; nb += hm2[j]*hm2[j]; }
  float gate = dot / fmaxf(sqrtf(na)*sqrtf(nb), EPS_COS);
#pragma unroll
  for (int j = 0; j < 4; j++) {
    int col = c0 + j;
    float o   = leaky(gate*hx2[j] + (1.f-gate)*hm2[j]);
    float mu  = bredsum(o, sh) * (1.f/B);
    float dd  = o - mu;
    float var = bredsum(dd*dd, sh) * (1.f/B);
    d_o[b*H+col] = g3[col]*dd*rsqrtf(var + EPS_BN) + b3[col];
  }
}

// ---------------- per-step: softmax + argmax + write probs -------------------
__global__ void __launch_bounds__(512) k_smax(int s, float* __restrict__ out) {
  __shared__ float se[V];
  __shared__ float sh[512];
  __shared__ int   shi[512];
  int b = blockIdx.x, t = threadIdx.x;
  const float* row = d_logits + (size_t)b*V;
  float m = -3.0e38f;
  for (int v = t; v < V; v += 512) m = fmaxf(m, row[v]);
  sh[t] = m; __syncthreads();
#pragma unroll
  for (int o = 256; o > 0; o >>= 1) { if (t < o) sh[t] = fmaxf(sh[t], sh[t+o]); __syncthreads(); }
  m = sh[0]; __syncthreads();
  float sum = 0.f;
  for (int v = t; v < V; v += 512) { float e = expf(row[v]-m); se[v] = e; sum += e; }
  sh[t] = sum; __syncthreads();
#pragma unroll
  for (int o = 256; o > 0; o >>= 1) { if (t < o) sh[t] += sh[t+o]; __syncthreads(); }
  sum = sh[0]; __syncthreads();
  float best = -1.f; int bi = 0;
  float* orow = out + (size_t)b*S*V + (size_t)s*V;
  for (int v = t; v < V; v += 512) {
    float p = se[v] / sum;
    orow[v] = p;
    if (p > best) { best = p; bi = v; }
  }
  sh[t] = best; shi[t] = bi; __syncthreads();
#pragma unroll
  for (int o = 256; o > 0; o >>= 1) {
    if (t < o) {
      float ov = sh[t+o]; int oi = shi[t+o];
      if (ov > sh[t] || (ov == sh[t] && oi < shi[t])) { sh[t] = ov; shi[t] = oi; }
    }
    __syncthreads();
  }
  if (t == 0) d_prev[b] = shi[0];
}

// ---------------- launch ------------------------------------------------------
extern "C" void kernel_launch(void* const* d_in, const int* in_sizes, int n_in,
                              void* d_out, int out_size) {
  const float* z      = (const float*)d_in[0];
  const float* temp   = (const float*)d_in[1];
  const float* z2h_w  = (const float*)d_in[2];
  const float* z2h_b  = (const float*)d_in[3];
  const float* bn1_g  = (const float*)d_in[4];
  const float* bn1_b  = (const float*)d_in[5];
  const float* emb    = (const float*)d_in[6];
  const float* bn2_g  = (const float*)d_in[7];
  const float* bn2_b  = (const float*)d_in[8];
  const float* memory = (const float*)d_in[9];
  const float* gx_wih = (const float*)d_in[10];
  const float* gx_whh = (const float*)d_in[11];
  const float* gx_bih = (const float*)d_in[12];
  const float* gx_bhh = (const float*)d_in[13];
  const float* gm_wih = (const float*)d_in[14];
  const float* gm_whh = (const float*)d_in[15];
  const float* gm_bih = (const float*)d_in[16];
  const float* gm_bhh = (const float*)d_in[17];
  const float* bn3_g  = (const float*)d_in[18];
  const float* bn3_b  = (const float*)d_in[19];
  const float* h2o_w  = (const float*)d_in[20];
  const float* h2o_b  = (const float*)d_in[21];
  float* out = (float*)d_out;

  k_keys  <<<1, 64>>>();
  k_gumbel<<<(S*(size_t)BV)/256, 256>>>();
  k_z0    <<<128, 128>>>(z, z2h_w, z2h_b, bn1_g, bn1_b);
  k_prep  <<<256, 256>>>();
  k_siz   <<<128, 128>>>(bn2_g, bn2_b);
  k_cz    <<<48, 256>>>(gx_wih, gx_bih);
  k_gim   <<<S, 256>>>(memory, gm_wih, gm_bih);

  for (int s = 0; s < S; s++) {
    k_embbn <<<128, 128>>>(emb, bn2_g, bn2_b);
    k_gemm3 <<<dim3(48,1,3), 256>>>(gx_wih, gx_whh, gm_whh, gx_bhh, gm_bhh);
    k_gru   <<<128, 128>>>(s, bn3_g, bn3_b);
    k_logits<<<256, 256>>>(s, h2o_w, h2o_b, temp);
    k_smax  <<<128, 512>>>(s, out);
  }
}

// round 14
// speedup vs baseline: 1.0614x; 1.0614x over previous
#include <cuda_runtime.h>
#include <math.h>

#define B   128
#define NZ  128
#define H   512
#define V   8192
#define S   64
#define H3  1536
#define EPS_BN  1e-5f
#define EPS_COS 1e-8f
#define NEG 0.2f
#define BV  (B*V)

// ---------------- static device scratch (allocations forbidden) ------------
__device__ __align__(16) float d_z0 [B*H];
__device__ __align__(16) float d_siz[B*H];
__device__ __align__(16) float d_cz [B*H3];
__device__ __align__(16) float d_gim[S*H3];
__device__ float d_g[(size_t)S*BV];           // 256 MiB gumbel noise
__device__ __align__(16) float d_six[B*H];
__device__ __align__(16) float d_gi [B*H3];
__device__ __align__(16) float d_ghx[B*H3];
__device__ __align__(16) float d_ghm[B*H3];
__device__ __align__(16) float d_hx [B*H];
__device__ __align__(16) float d_hm [B*H];
__device__ __align__(16) float d_o  [B*H];
__device__ float d_logits[B*V];
__device__ int   d_prev[B];
__device__ unsigned d_keys[2*S];

// ---------------- threefry2x32 (bit-exact vs JAX) --------------------------
__device__ __forceinline__ void threefry(unsigned k0, unsigned k1,
                                         unsigned c0, unsigned c1,
                                         unsigned &o0, unsigned &o1) {
  unsigned ks2 = k0 ^ k1 ^ 0x1BD11BDAu;
  unsigned x0 = c0 + k0, x1 = c1 + k1;
#define TFR(r) { x0 += x1; x1 = (x1 << (r)) | (x1 >> (32 - (r))); x1 ^= x0; }
  TFR(13) TFR(15) TFR(26) TFR(6)   x0 += k1;  x1 += ks2 + 1u;
  TFR(17) TFR(29) TFR(16) TFR(24)  x0 += ks2; x1 += k0 + 2u;
  TFR(13) TFR(15) TFR(26) TFR(6)   x0 += k0;  x1 += k1 + 3u;
  TFR(17) TFR(29) TFR(16) TFR(24)  x0 += k1;  x1 += ks2 + 4u;
  TFR(13) TFR(15) TFR(26) TFR(6)   x0 += ks2; x1 += k0 + 5u;
#undef TFR
  o0 = x0; o1 = x1;
}

__device__ __forceinline__ float gumbel_from_bits(unsigned bits) {
  float f = __uint_as_float((bits >> 9) | 0x3f800000u) - 1.0f;   // [0,1)
  float u = fmaxf(1e-6f, __fadd_rn(__fmul_rn(f, (1.0f - 1e-6f) - 1e-6f), 1e-6f));
  return -logf(-logf(u));
}

__global__ void k_keys() {
  int s = threadIdx.x;
  if (s < S) { unsigned o0,o1; threefry(0u,42u,0u,(unsigned)s,o0,o1);
               d_keys[2*s]=o0; d_keys[2*s+1]=o1; }
}

// Partitionable threefry random_bits: counter (0, i), 32-bit out = o0 ^ o1.
__global__ void k_gumbel() {
  int idx = blockIdx.x * blockDim.x + threadIdx.x;
  int s = idx / BV;
  int i = idx - s * BV;
  unsigned o0,o1;
  threefry(d_keys[2*s], d_keys[2*s+1], 0u, (unsigned)i, o0, o1);
  d_g[(size_t)s * BV + i] = gumbel_from_bits(o0 ^ o1);
}

// ---------------- helpers ---------------------------------------------------
__device__ __forceinline__ float bredsum(float v, float* sh) {
  int t = threadIdx.x;
  sh[t] = v; __syncthreads();
#pragma unroll
  for (int o = 64; o > 0; o >>= 1) { if (t < o) sh[t] += sh[t+o]; __syncthreads(); }
  float r = sh[0]; __syncthreads();
  return r;
}
__device__ __forceinline__ float leaky(float x) { return x >= 0.f ? x : NEG*x; }
__device__ __forceinline__ float sig(float x)   { return 1.f/(1.f+expf(-x)); }

#define FFMA2(acc, a, b) \
  asm("fma.rn.f32x2 %0, %1, %2, %0;" : "+l"(acc) : "l"(a), "l"(b))
#define PACK2(out, x) \
  asm("mov.b64 %0, {%1, %1};" : "=l"(out) : "r"(__float_as_uint(x)))

union U64F2 { unsigned long long u; float2 f; };

// ---------------- setup kernels ---------------------------------------------
__global__ void k_z0(const float* __restrict__ z, const float* __restrict__ w,
                     const float* __restrict__ bias, const float* __restrict__ gg,
                     const float* __restrict__ bb) {
  __shared__ float sh[128];
  int b = threadIdx.x, c0 = blockIdx.x * 4;
  const float* zr = z + b*NZ;
  for (int j = 0; j < 4; j++) {
    int col = c0 + j;
    float acc = bias[col];
    const float* wr = w + col*NZ;
    for (int k = 0; k < NZ; k++) acc = fmaf(zr[k], wr[k], acc);
    float v   = leaky(acc);
    float mu  = bredsum(v, sh) * (1.f/B);
    float dd  = v - mu;
    float var = bredsum(dd*dd, sh) * (1.f/B);
    d_z0[b*H + col] = gg[col]*dd*rsqrtf(var + EPS_BN) + bb[col];
  }
}

__global__ void k_prep() {
  int i = blockIdx.x * blockDim.x + threadIdx.x;
  if (i < B*H) { float v = d_z0[i]; d_hx[i] = v; d_hm[i] = v; }
  if (i < B) d_prev[i] = V - 1;
}

__global__ void k_siz(const float* __restrict__ g2, const float* __restrict__ b2) {
  __shared__ float sh[128];
  int b = threadIdx.x, c0 = blockIdx.x * 4;
  for (int j = 0; j < 4; j++) {
    int col = c0 + j;
    float v   = d_z0[b*H + col];
    float mu  = bredsum(v, sh) * (1.f/B);
    float dd  = v - mu;
    float var = bredsum(dd*dd, sh) * (1.f/B);
    d_siz[b*H + col] = g2[H+col]*dd*rsqrtf(var + EPS_BN) + b2[H+col];
  }
}

__global__ void k_gim(const float* __restrict__ mem, const float* __restrict__ W,
                      const float* __restrict__ bias) {
  __shared__ float a[2*H];
  int s = blockIdx.x;
  for (int k = threadIdx.x; k < 2*H; k += 256) a[k] = mem[(size_t)s*2*H + k];
  __syncthreads();
  for (int n = threadIdx.x; n < H3; n += 256) {
    float acc = bias[n];
    const float* w = W + (size_t)n*2*H;
    for (int k = 0; k < 2*H; k++) acc = fmaf(a[k], w[k], acc);
    d_gim[s*H3 + n] = acc;
  }
}

__global__ void k_embbn(const float* __restrict__ emb,
                        const float* __restrict__ g2, const float* __restrict__ b2) {
  __shared__ float sh[128];
  int b = threadIdx.x, c0 = blockIdx.x * 4;
  const float* er = emb + (size_t)d_prev[b]*H;
  for (int j = 0; j < 4; j++) {
    int col = c0 + j;
    float e   = leaky(er[col]);
    float mu  = bredsum(e, sh) * (1.f/B);
    float dd  = e - mu;
    float var = bredsum(dd*dd, sh) * (1.f/B);
    d_six[b*H + col] = g2[col]*dd*rsqrtf(var + EPS_BN) + b2[col];
  }
}

// ---------------- tiled fp32 GEMM core (R7), K-chunk 32 + prefetch ----------
template <int RPT>
__device__ __forceinline__ void gemm_core(
    const float* __restrict__ A, const float* __restrict__ W, int ldw,
    const float* __restrict__ bias, const float* __restrict__ addM, int ldadd,
    float* __restrict__ C, int ldc, int n0,
    const float* __restrict__ gbase, float t) {
  constexpr int NT = 8 * RPT;
  constexpr int TX = NT / 4;
  constexpr int WF = (NT * 8) / 256;
  __shared__ __align__(16) float Ash[32][132];
  __shared__ __align__(16) float Wsh[32][NT + 4];
  int tid = threadIdx.x;
  int tx = tid % TX, ty = tid / TX;
  int r0 = ty * RPT, c0 = tx * 4;
  float acc[RPT][4];
#pragma unroll
  for (int j = 0; j < RPT; j++)
#pragma unroll
    for (int c = 0; c < 4; c++) acc[j][c] = 0.f;

  float4 aR[4], wR[WF];
#pragma unroll
  for (int i = 0; i < 4; i++) {
    int e = tid + i*256; int row = e >> 3, kq = e & 7;
    aR[i] = *(const float4*)(A + row*512 + kq*4);
  }
#pragma unroll
  for (int i = 0; i < WF; i++) {
    int e = tid + i*256; int wr = e >> 3, kq = e & 7;
    wR[i] = *(const float4*)(W + (size_t)(n0+wr)*ldw + kq*4);
  }

  for (int it = 0; it < 16; it++) {
#pragma unroll
    for (int i = 0; i < 4; i++) {
      int e = tid + i*256; int row = e >> 3, kq = e & 7;
      Ash[kq*4+0][row] = aR[i].x; Ash[kq*4+1][row] = aR[i].y;
      Ash[kq*4+2][row] = aR[i].z; Ash[kq*4+3][row] = aR[i].w;
    }
#pragma unroll
    for (int i = 0; i < WF; i++) {
      int e = tid + i*256; int wr = e >> 3, kq = e & 7;
      Wsh[kq*4+0][wr] = wR[i].x; Wsh[kq*4+1][wr] = wR[i].y;
      Wsh[kq*4+2][wr] = wR[i].z; Wsh[kq*4+3][wr] = wR[i].w;
    }
    __syncthreads();
    if (it < 15) {
      int kt = (it+1) * 32;
#pragma unroll
      for (int i = 0; i < 4; i++) {
        int e = tid + i*256; int row = e >> 3, kq = e & 7;
        aR[i] = *(const float4*)(A + row*512 + kt + kq*4);
      }
#pragma unroll
      for (int i = 0; i < WF; i++) {
        int e = tid + i*256; int wr = e >> 3, kq = e & 7;
        wR[i] = *(const float4*)(W + (size_t)(n0+wr)*ldw + kt + kq*4);
      }
    }
#pragma unroll
    for (int kk = 0; kk < 32; kk++) {
      float av[RPT];
#pragma unroll
      for (int q = 0; q < RPT/4; q++) {
        float4 aa = *(const float4*)&Ash[kk][r0 + q*4];
        av[q*4+0]=aa.x; av[q*4+1]=aa.y; av[q*4+2]=aa.z; av[q*4+3]=aa.w;
      }
      float4 ww = *(const float4*)&Wsh[kk][c0];
      float wv4[4] = {ww.x, ww.y, ww.z, ww.w};
#pragma unroll
      for (int j = 0; j < RPT; j++)
#pragma unroll
        for (int c = 0; c < 4; c++)
          acc[j][c] = fmaf(av[j], wv4[c], acc[j][c]);
    }
    __syncthreads();
  }
#pragma unroll
  for (int j = 0; j < RPT; j++) {
    int row = r0 + j;
#pragma unroll
    for (int c = 0; c < 4; c++) {
      int col = n0 + c0 + c;
      float v = acc[j][c];
      if (bias)  v += bias[col];
      if (addM)  v += addM[(size_t)row*ldadd + col];
      if (gbase) v = (v + gbase[(size_t)row*V + col]) / t;
      C[(size_t)row*ldc + col] = v;
    }
  }
}

__global__ void __launch_bounds__(256) k_cz(const float* __restrict__ W,
                                            const float* __restrict__ bias) {
  gemm_core<4>(d_siz, W + H, 2*H, bias, (const float*)0, 0,
               d_cz, H3, blockIdx.x*32, (const float*)0, 1.f);
}

__global__ void __launch_bounds__(256) k_gemm3(
    const float* __restrict__ wih_x, const float* __restrict__ whh_x,
    const float* __restrict__ whh_m, const float* __restrict__ bhh_x,
    const float* __restrict__ bhh_m) {
  int n0 = blockIdx.x * 32;
  int z = blockIdx.z;
  const float* A    = (z==0) ? d_six : (z==1) ? d_hx : d_hm;
  const float* W    = (z==0) ? wih_x : (z==1) ? whh_x : whh_m;
  int ldw           = (z==0) ? 2*H : H;
  const float* bias = (z==0) ? (const float*)0 : (z==1) ? bhh_x : bhh_m;
  const float* addM = (z==0) ? d_cz : (const float*)0;
  float* Cm         = (z==0) ? d_gi : (z==1) ? d_ghx : d_ghm;
  gemm_core<4>(A, W, ldw, bias, addM, H3, Cm, H3, n0, (const float*)0, 1.f);
}

// ---------------- FFMA2 logits GEMM ------------------------------------------
// Same staging/smem/K-order as gemm_core<8>; inner loop uses fma.rn.f32x2 on
// row-pairs with W pairs packed in registers. Each f32x2 lane is an
// independent FMA chain in identical K order -> logits bit-identical to R7.
__global__ void __launch_bounds__(256) k_logits(
    int s, const float* __restrict__ W, const float* __restrict__ bias,
    const float* __restrict__ tptr) {
  __shared__ __align__(16) float Ash[32][132];
  __shared__ __align__(16) float Wsh[32][68];
  int tid = threadIdx.x;
  int tx = tid & 15, ty = tid >> 4;          // 16 col-groups x 16 row-groups
  int r0 = ty * 8, c0 = tx * 4;
  int n0 = blockIdx.x * 64;
  const float* A = d_o;

  unsigned long long acc[4][4];
#pragma unroll
  for (int p = 0; p < 4; p++)
#pragma unroll
    for (int c = 0; c < 4; c++) acc[p][c] = 0ull;

  float4 aR[4], wR[2];
#pragma unroll
  for (int i = 0; i < 4; i++) {
    int e = tid + i*256; int row = e >> 3, kq = e & 7;
    aR[i] = *(const float4*)(A + row*512 + kq*4);
  }
#pragma unroll
  for (int i = 0; i < 2; i++) {
    int e = tid + i*256; int wr = e >> 3, kq = e & 7;
    wR[i] = *(const float4*)(W + (size_t)(n0+wr)*H + kq*4);
  }

  for (int it = 0; it < 16; it++) {
#pragma unroll
    for (int i = 0; i < 4; i++) {
      int e = tid + i*256; int row = e >> 3, kq = e & 7;
      Ash[kq*4+0][row] = aR[i].x; Ash[kq*4+1][row] = aR[i].y;
      Ash[kq*4+2][row] = aR[i].z; Ash[kq*4+3][row] = aR[i].w;
    }
#pragma unroll
    for (int i = 0; i < 2; i++) {
      int e = tid + i*256; int wr = e >> 3, kq = e & 7;
      Wsh[kq*4+0][wr] = wR[i].x; Wsh[kq*4+1][wr] = wR[i].y;
      Wsh[kq*4+2][wr] = wR[i].z; Wsh[kq*4+3][wr] = wR[i].w;
    }
    __syncthreads();
    if (it < 15) {
      int kt = (it+1) * 32;
#pragma unroll
      for (int i = 0; i < 4; i++) {
        int e = tid + i*256; int row = e >> 3, kq = e & 7;
        aR[i] = *(const float4*)(A + row*512 + kt + kq*4);
      }
#pragma unroll
      for (int i = 0; i < 2; i++) {
        int e = tid + i*256; int wr = e >> 3, kq = e & 7;
        wR[i] = *(const float4*)(W + (size_t)(n0+wr)*H + kt + kq*4);
      }
    }
#pragma unroll
    for (int kk = 0; kk < 32; kk++) {
      // A rows r0..r0+7 as 4 packed pairs (rows (0,1),(2,3),(4,5),(6,7))
      ulonglong2 a01 = *(const ulonglong2*)&Ash[kk][r0];
      ulonglong2 a23 = *(const ulonglong2*)&Ash[kk][r0 + 4];
      float4 ww = *(const float4*)&Wsh[kk][c0];
      unsigned long long w0, w1, w2, w3;
      PACK2(w0, ww.x); PACK2(w1, ww.y); PACK2(w2, ww.z); PACK2(w3, ww.w);
      FFMA2(acc[0][0], a01.x, w0); FFMA2(acc[0][1], a01.x, w1);
      FFMA2(acc[0][2], a01.x, w2); FFMA2(acc[0][3], a01.x, w3);
      FFMA2(acc[1][0], a01.y, w0); FFMA2(acc[1][1], a01.y, w1);
      FFMA2(acc[1][2], a01.y, w2); FFMA2(acc[1][3], a01.y, w3);
      FFMA2(acc[2][0], a23.x, w0); FFMA2(acc[2][1], a23.x, w1);
      FFMA2(acc[2][2], a23.x, w2); FFMA2(acc[2][3], a23.x, w3);
      FFMA2(acc[3][0], a23.y, w0); FFMA2(acc[3][1], a23.y, w1);
      FFMA2(acc[3][2], a23.y, w2); FFMA2(acc[3][3], a23.y, w3);
    }
    __syncthreads();
  }
  float t = *tptr;
  const float* gb = d_g + (size_t)s*BV;
#pragma unroll
  for (int p = 0; p < 4; p++) {
    int ra = r0 + 2*p, rb = ra + 1;
#pragma unroll
    for (int c = 0; c < 4; c++) {
      int col = n0 + c0 + c;
      U64F2 u; u.u = acc[p][c];
      float bv = bias[col];
      d_logits[(size_t)ra*V + col] = (u.f.x + bv + gb[(size_t)ra*V + col]) / t;
      d_logits[(size_t)rb*V + col] = (u.f.y + bv + gb[(size_t)rb*V + col]) / t;
    }
  }
}

// ---------------- per-step: GRU combine + cosine gate + bn3 ------------------
__global__ void k_gru(int s, const float* __restrict__ g3, const float* __restrict__ b3) {
  __shared__ float sh[128];
  int b = threadIdx.x, c0 = blockIdx.x * 4;
  const float* gim = d_gim + s*H3;
  float hx2[4], hm2[4];
#pragma unroll
  for (int j = 0; j < 4; j++) {
    int col = c0 + j;
    float ir = d_gi [b*H3+col], iz = d_gi [b*H3+H+col], in_ = d_gi [b*H3+2*H+col];
    float hr = d_ghx[b*H3+col], hz = d_ghx[b*H3+H+col], hn  = d_ghx[b*H3+2*H+col];
    float h  = d_hx[b*H+col];
    float r  = sig(ir+hr), zg = sig(iz+hz);
    float n  = tanhf(in_ + r*hn);
    hx2[j] = (1.f-zg)*n + zg*h;
    float mir = gim[col], miz = gim[H+col], min_ = gim[2*H+col];
    float mhr = d_ghm[b*H3+col], mhz = d_ghm[b*H3+H+col], mhn = d_ghm[b*H3+2*H+col];
    float hmv = d_hm[b*H+col];
    float rm  = sig(mir+mhr), zm = sig(miz+mhz);
    float nm  = tanhf(min_ + rm*mhn);
    hm2[j] = (1.f-zm)*nm + zm*hmv;
    d_hx[b*H+col] = hx2[j];
    d_hm[b*H+col] = hm2[j];
  }
  float dot=0.f, na=0.f, nb=0.f;
#pragma unroll
  for (int j = 0; j < 4; j++) { dot += hx2[j]*hm2[j]; na += hx2[j]*hx2[j]; nb += hm2[j]*hm2[j]; }
  float gate = dot / fmaxf(sqrtf(na)*sqrtf(nb), EPS_COS);
#pragma unroll
  for (int j = 0; j < 4; j++) {
    int col = c0 + j;
    float o   = leaky(gate*hx2[j] + (1.f-gate)*hm2[j]);
    float mu  = bredsum(o, sh) * (1.f/B);
    float dd  = o - mu;
    float var = bredsum(dd*dd, sh) * (1.f/B);
    d_o[b*H+col] = g3[col]*dd*rsqrtf(var + EPS_BN) + b3[col];
  }
}

// ---------------- per-step: softmax + argmax + write probs -------------------
__global__ void __launch_bounds__(512) k_smax(int s, float* __restrict__ out) {
  __shared__ float se[V];
  __shared__ float sh[512];
  __shared__ int   shi[512];
  int b = blockIdx.x, t = threadIdx.x;
  const float* row = d_logits + (size_t)b*V;
  float m = -3.0e38f;
  for (int v = t; v < V; v += 512) m = fmaxf(m, row[v]);
  sh[t] = m; __syncthreads();
#pragma unroll
  for (int o = 256; o > 0; o >>= 1) { if (t < o) sh[t] = fmaxf(sh[t], sh[t+o]); __syncthreads(); }
  m = sh[0]; __syncthreads();
  float sum = 0.f;
  for (int v = t; v < V; v += 512) { float e = expf(row[v]-m); se[v] = e; sum += e; }
  sh[t] = sum; __syncthreads();
#pragma unroll
  for (int o = 256; o > 0; o >>= 1) { if (t < o) sh[t] += sh[t+o]; __syncthreads(); }
  sum = sh[0]; __syncthreads();
  float best = -1.f; int bi = 0;
  float* orow = out + (size_t)b*S*V + (size_t)s*V;
  for (int v = t; v < V; v += 512) {
    float p = se[v] / sum;
    orow[v] = p;
    if (p > best) { best = p; bi = v; }
  }
  sh[t] = best; shi[t] = bi; __syncthreads();
#pragma unroll
  for (int o = 256; o > 0; o >>= 1) {
    if (t < o) {
      float ov = sh[t+o]; int oi = shi[t+o];
      if (ov > sh[t] || (ov == sh[t] && oi < shi[t])) { sh[t] = ov; shi[t] = oi; }
    }
    __syncthreads();
  }
  if (t == 0) d_prev[b] = shi[0];
}

// ---------------- launch ------------------------------------------------------
extern "C" void kernel_launch(void* const* d_in, const int* in_sizes, int n_in,
                              void* d_out, int out_size) {
  const float* z      = (const float*)d_in[0];
  const float* temp   = (const float*)d_in[1];
  const float* z2h_w  = (const float*)d_in[2];
  const float* z2h_b  = (const float*)d_in[3];
  const float* bn1_g  = (const float*)d_in[4];
  const float* bn1_b  = (const float*)d_in[5];
  const float* emb    = (const float*)d_in[6];
  const float* bn2_g  = (const float*)d_in[7];
  const float* bn2_b  = (const float*)d_in[8];
  const float* memory = (const float*)d_in[9];
  const float* gx_wih = (const float*)d_in[10];
  const float* gx_whh = (const float*)d_in[11];
  const float* gx_bih = (const float*)d_in[12];
  const float* gx_bhh = (const float*)d_in[13];
  const float* gm_wih = (const float*)d_in[14];
  const float* gm_whh = (const float*)d_in[15];
  const float* gm_bih = (const float*)d_in[16];
  const float* gm_bhh = (const float*)d_in[17];
  const float* bn3_g  = (const float*)d_in[18];
  const float* bn3_b  = (const float*)d_in[19];
  const float* h2o_w  = (const float*)d_in[20];
  const float* h2o_b  = (const float*)d_in[21];
  float* out = (float*)d_out;

  k_keys  <<<1, 64>>>();
  k_gumbel<<<(S*(size_t)BV)/256, 256>>>();
  k_z0    <<<128, 128>>>(z, z2h_w, z2h_b, bn1_g, bn1_b);
  k_prep  <<<256, 256>>>();
  k_siz   <<<128, 128>>>(bn2_g, bn2_b);
  k_cz    <<<48, 256>>>(gx_wih, gx_bih);
  k_gim   <<<S, 256>>>(memory, gm_wih, gm_bih);

  for (int s = 0; s < S; s++) {
    k_embbn <<<128, 128>>>(emb, bn2_g, bn2_b);
    k_gemm3 <<<dim3(48,1,3), 256>>>(gx_wih, gx_whh, gm_whh, gx_bhh, gm_bhh);
    k_gru   <<<128, 128>>>(s, bn3_g, bn3_b);
    k_logits<<<128, 256>>>(s, h2o_w, h2o_b, temp);
    k_smax  <<<128, 512>>>(s, out);
  }
}

// round 15
// speedup vs baseline: 1.0619x; 1.0004x over previous
#include <cuda_runtime.h>
#include <math.h>

#define B   128
#define NZ  128
#define H   512
#define V   8192
#define S   64
#define H3  1536
#define EPS_BN  1e-5f
#define EPS_COS 1e-8f
#define NEG 0.2f
#define BV  (B*V)

// ---------------- static device scratch (allocations forbidden) ------------
__device__ __align__(16) float d_z0 [B*H];
__device__ __align__(16) float d_siz[B*H];
__device__ __align__(16) float d_cz [B*H3];
__device__ __align__(16) float d_gim[S*H3];
__device__ float d_g[(size_t)S*BV];           // 256 MiB gumbel noise
__device__ __align__(16) float d_six[B*H];
__device__ __align__(16) float d_gi [B*H3];
__device__ __align__(16) float d_ghx[B*H3];
__device__ __align__(16) float d_ghm[B*H3];
__device__ __align__(16) float d_hx [B*H];
__device__ __align__(16) float d_hm [B*H];
__device__ __align__(16) float d_o  [B*H];
__device__ float d_logits[B*V];
__device__ int   d_prev[B];
__device__ unsigned d_keys[2*S];

// ---------------- threefry2x32 (bit-exact vs JAX) --------------------------
__device__ __forceinline__ void threefry(unsigned k0, unsigned k1,
                                         unsigned c0, unsigned c1,
                                         unsigned &o0, unsigned &o1) {
  unsigned ks2 = k0 ^ k1 ^ 0x1BD11BDAu;
  unsigned x0 = c0 + k0, x1 = c1 + k1;
#define TFR(r) { x0 += x1; x1 = __funnelshift_l(x1, x1, (r)); x1 ^= x0; }
  TFR(13) TFR(15) TFR(26) TFR(6)   x0 += k1;  x1 += ks2 + 1u;
  TFR(17) TFR(29) TFR(16) TFR(24)  x0 += ks2; x1 += k0 + 2u;
  TFR(13) TFR(15) TFR(26) TFR(6)   x0 += k0;  x1 += k1 + 3u;
  TFR(17) TFR(29) TFR(16) TFR(24)  x0 += k1;  x1 += ks2 + 4u;
  TFR(13) TFR(15) TFR(26) TFR(6)   x0 += ks2; x1 += k0 + 5u;
#undef TFR
  o0 = x0; o1 = x1;
}

// full-precision ln via atanh-form polynomial (~1-2 ulp), u in (0, 1)
__device__ __forceinline__ float fast_ln(float u) {
  int ix = __float_as_int(u);
  int e  = (ix - 0x3f3504f3) >> 23;              // split at sqrt(0.5)
  float m = __int_as_float(ix - (e << 23));      // m in [0.7071, 1.4142)
  float s = m - 1.0f;
  float d = 2.0f + s;
  float rd; asm("rcp.approx.f32 %0, %1;" : "=f"(rd) : "f"(d));
  float t  = s * rd;                             // atanh argument
  float t2 = t * t;
  float w  = fmaf(fmaf(fmaf(0.14285714f, t2, 0.2f), t2, 0.33333334f), t2, 1.0f);
  float fe = (float)e;
  float lo = fmaf(2.0f * t, w, fe * 1.4286068e-6f);
  return fmaf(fe, 0.69314575f, lo);              // ln2 hi/lo split
}

__device__ __forceinline__ float gumbel_from_bits(unsigned bits) {
  float f = __uint_as_float((bits >> 9) | 0x3f800000u) - 1.0f;   // [0,1)
  // JAX: max(minval, u*(maxval-minval)+minval), mul+add unfused
  float u = fmaxf(1e-6f, __fadd_rn(__fmul_rn(f, (1.0f - 1e-6f) - 1e-6f), 1e-6f));
  float x = -fast_ln(u);                         // in [1.1e-6, 13.9]
  float lx; asm("lg2.approx.f32 %0, %1;" : "=f"(lx) : "f"(x));
  return -0.69314718f * lx;                      // -ln(x)
}

__global__ void k_keys() {
  int s = threadIdx.x;
  if (s < S) { unsigned o0,o1; threefry(0u,42u,0u,(unsigned)s,o0,o1);
               d_keys[2*s]=o0; d_keys[2*s+1]=o1; }
}

// Partitionable threefry random_bits: counter (0, i), 32-bit out = o0 ^ o1.
__global__ void k_gumbel() {
  int idx = blockIdx.x * blockDim.x + threadIdx.x;
  int s = idx / BV;
  int i = idx - s * BV;
  unsigned o0,o1;
  threefry(d_keys[2*s], d_keys[2*s+1], 0u, (unsigned)i, o0, o1);
  d_g[(size_t)s * BV + i] = gumbel_from_bits(o0 ^ o1);
}

// ---------------- helpers ---------------------------------------------------
__device__ __forceinline__ float bredsum(float v, float* sh) {
  int t = threadIdx.x;
  sh[t] = v; __syncthreads();
#pragma unroll
  for (int o = 64; o > 0; o >>= 1) { if (t < o) sh[t] += sh[t+o]; __syncthreads(); }
  float r = sh[0]; __syncthreads();
  return r;
}
__device__ __forceinline__ float leaky(float x) { return x >= 0.f ? x : NEG*x; }
__device__ __forceinline__ float sig(float x)   { return 1.f/(1.f+expf(-x)); }

#define FFMA2(acc, a, b) \
  asm("fma.rn.f32x2 %0, %1, %2, %0;" : "+l"(acc) : "l"(a), "l"(b))
#define PACK2(out, x) \
  asm("mov.b64 %0, {%1, %1};" : "=l"(out) : "r"(__float_as_uint(x)))

union U64F2 { unsigned long long u; float2 f; };

// ---------------- setup kernels ---------------------------------------------
__global__ void k_z0(const float* __restrict__ z, const float* __restrict__ w,
                     const float* __restrict__ bias, const float* __restrict__ gg,
                     const float* __restrict__ bb) {
  __shared__ float sh[128];
  int b = threadIdx.x, c0 = blockIdx.x * 4;
  const float* zr = z + b*NZ;
  for (int j = 0; j < 4; j++) {
    int col = c0 + j;
    float acc = bias[col];
    const float* wr = w + col*NZ;
    for (int k = 0; k < NZ; k++) acc = fmaf(zr[k], wr[k], acc);
    float v   = leaky(acc);
    float mu  = bredsum(v, sh) * (1.f/B);
    float dd  = v - mu;
    float var = bredsum(dd*dd, sh) * (1.f/B);
    d_z0[b*H + col] = gg[col]*dd*rsqrtf(var + EPS_BN) + bb[col];
  }
}

__global__ void k_prep() {
  int i = blockIdx.x * blockDim.x + threadIdx.x;
  if (i < B*H) { float v = d_z0[i]; d_hx[i] = v; d_hm[i] = v; }
  if (i < B) d_prev[i] = V - 1;
}

__global__ void k_siz(const float* __restrict__ g2, const float* __restrict__ b2) {
  __shared__ float sh[128];
  int b = threadIdx.x, c0 = blockIdx.x * 4;
  for (int j = 0; j < 4; j++) {
    int col = c0 + j;
    float v   = d_z0[b*H + col];
    float mu  = bredsum(v, sh) * (1.f/B);
    float dd  = v - mu;
    float var = bredsum(dd*dd, sh) * (1.f/B);
    d_siz[b*H + col] = g2[H+col]*dd*rsqrtf(var + EPS_BN) + b2[H+col];
  }
}

__global__ void k_gim(const float* __restrict__ mem, const float* __restrict__ W,
                      const float* __restrict__ bias) {
  __shared__ float a[2*H];
  int s = blockIdx.x;
  for (int k = threadIdx.x; k < 2*H; k += 256) a[k] = mem[(size_t)s*2*H + k];
  __syncthreads();
  for (int n = threadIdx.x; n < H3; n += 256) {
    float acc = bias[n];
    const float* w = W + (size_t)n*2*H;
    for (int k = 0; k < 2*H; k++) acc = fmaf(a[k], w[k], acc);
    d_gim[s*H3 + n] = acc;
  }
}

__global__ void k_embbn(const float* __restrict__ emb,
                        const float* __restrict__ g2, const float* __restrict__ b2) {
  __shared__ float sh[128];
  int b = threadIdx.x, c0 = blockIdx.x * 4;
  const float* er = emb + (size_t)d_prev[b]*H;
  for (int j = 0; j < 4; j++) {
    int col = c0 + j;
    float e   = leaky(er[col]);
    float mu  = bredsum(e, sh) * (1.f/B);
    float dd  = e - mu;
    float var = bredsum(dd*dd, sh) * (1.f/B);
    d_six[b*H + col] = g2[col]*dd*rsqrtf(var + EPS_BN) + b2[col];
  }
}

// ---------------- tiled fp32 GEMM core (R7), K-chunk 32 + prefetch ----------
template <int RPT>
__device__ __forceinline__ void gemm_core(
    const float* __restrict__ A, const float* __restrict__ W, int ldw,
    const float* __restrict__ bias, const float* __restrict__ addM, int ldadd,
    float* __restrict__ C, int ldc, int n0,
    const float* __restrict__ gbase, float t) {
  constexpr int NT = 8 * RPT;
  constexpr int TX = NT / 4;
  constexpr int WF = (NT * 8) / 256;
  __shared__ __align__(16) float Ash[32][132];
  __shared__ __align__(16) float Wsh[32][NT + 4];
  int tid = threadIdx.x;
  int tx = tid % TX, ty = tid / TX;
  int r0 = ty * RPT, c0 = tx * 4;
  float acc[RPT][4];
#pragma unroll
  for (int j = 0; j < RPT; j++)
#pragma unroll
    for (int c = 0; c < 4; c++) acc[j][c] = 0.f;

  float4 aR[4], wR[WF];
#pragma unroll
  for (int i = 0; i < 4; i++) {
    int e = tid + i*256; int row = e >> 3, kq = e & 7;
    aR[i] = *(const float4*)(A + row*512 + kq*4);
  }
#pragma unroll
  for (int i = 0; i < WF; i++) {
    int e = tid + i*256; int wr = e >> 3, kq = e & 7;
    wR[i] = *(const float4*)(W + (size_t)(n0+wr)*ldw + kq*4);
  }

  for (int it = 0; it < 16; it++) {
#pragma unroll
    for (int i = 0; i < 4; i++) {
      int e = tid + i*256; int row = e >> 3, kq = e & 7;
      Ash[kq*4+0][row] = aR[i].x; Ash[kq*4+1][row] = aR[i].y;
      Ash[kq*4+2][row] = aR[i].z; Ash[kq*4+3][row] = aR[i].w;
    }
#pragma unroll
    for (int i = 0; i < WF; i++) {
      int e = tid + i*256; int wr = e >> 3, kq = e & 7;
      Wsh[kq*4+0][wr] = wR[i].x; Wsh[kq*4+1][wr] = wR[i].y;
      Wsh[kq*4+2][wr] = wR[i].z; Wsh[kq*4+3][wr] = wR[i].w;
    }
    __syncthreads();
    if (it < 15) {
      int kt = (it+1) * 32;
#pragma unroll
      for (int i = 0; i < 4; i++) {
        int e = tid + i*256; int row = e >> 3, kq = e & 7;
        aR[i] = *(const float4*)(A + row*512 + kt + kq*4);
      }
#pragma unroll
      for (int i = 0; i < WF; i++) {
        int e = tid + i*256; int wr = e >> 3, kq = e & 7;
        wR[i] = *(const float4*)(W + (size_t)(n0+wr)*ldw + kt + kq*4);
      }
    }
#pragma unroll
    for (int kk = 0; kk < 32; kk++) {
      float av[RPT];
#pragma unroll
      for (int q = 0; q < RPT/4; q++) {
        float4 aa = *(const float4*)&Ash[kk][r0 + q*4];
        av[q*4+0]=aa.x; av[q*4+1]=aa.y; av[q*4+2]=aa.z; av[q*4+3]=aa.w;
      }
      float4 ww = *(const float4*)&Wsh[kk][c0];
      float wv4[4] = {ww.x, ww.y, ww.z, ww.w};
#pragma unroll
      for (int j = 0; j < RPT; j++)
#pragma unroll
        for (int c = 0; c < 4; c++)
          acc[j][c] = fmaf(av[j], wv4[c], acc[j][c]);
    }
    __syncthreads();
  }
#pragma unroll
  for (int j = 0; j < RPT; j++) {
    int row = r0 + j;
#pragma unroll
    for (int c = 0; c < 4; c++) {
      int col = n0 + c0 + c;
      float v = acc[j][c];
      if (bias)  v += bias[col];
      if (addM)  v += addM[(size_t)row*ldadd + col];
      if (gbase) v = (v + gbase[(size_t)row*V + col]) / t;
      C[(size_t)row*ldc + col] = v;
    }
  }
}

__global__ void __launch_bounds__(256) k_cz(const float* __restrict__ W,
                                            const float* __restrict__ bias) {
  gemm_core<4>(d_siz, W + H, 2*H, bias, (const float*)0, 0,
               d_cz, H3, blockIdx.x*32, (const float*)0, 1.f);
}

__global__ void __launch_bounds__(256) k_gemm3(
    const float* __restrict__ wih_x, const float* __restrict__ whh_x,
    const float* __restrict__ whh_m, const float* __restrict__ bhh_x,
    const float* __restrict__ bhh_m) {
  int n0 = blockIdx.x * 32;
  int z = blockIdx.z;
  const float* A    = (z==0) ? d_six : (z==1) ? d_hx : d_hm;
  const float* W    = (z==0) ? wih_x : (z==1) ? whh_x : whh_m;
  int ldw           = (z==0) ? 2*H : H;
  const float* bias = (z==0) ? (const float*)0 : (z==1) ? bhh_x : bhh_m;
  const float* addM = (z==0) ? d_cz : (const float*)0;
  float* Cm         = (z==0) ? d_gi : (z==1) ? d_ghx : d_ghm;
  gemm_core<4>(A, W, ldw, bias, addM, H3, Cm, H3, n0, (const float*)0, 1.f);
}

// ---------------- FFMA2 logits GEMM (R14 best) --------------------------------
__global__ void __launch_bounds__(256) k_logits(
    int s, const float* __restrict__ W, const float* __restrict__ bias,
    const float* __restrict__ tptr) {
  __shared__ __align__(16) float Ash[32][132];
  __shared__ __align__(16) float Wsh[32][68];
  int tid = threadIdx.x;
  int tx = tid & 15, ty = tid >> 4;
  int r0 = ty * 8, c0 = tx * 4;
  int n0 = blockIdx.x * 64;
  const float* A = d_o;

  unsigned long long acc[4][4];
#pragma unroll
  for (int p = 0; p < 4; p++)
#pragma unroll
    for (int c = 0; c < 4; c++) acc[p][c] = 0ull;

  float4 aR[4], wR[2];
#pragma unroll
  for (int i = 0; i < 4; i++) {
    int e = tid + i*256; int row = e >> 3, kq = e & 7;
    aR[i] = *(const float4*)(A + row*512 + kq*4);
  }
#pragma unroll
  for (int i = 0; i < 2; i++) {
    int e = tid + i*256; int wr = e >> 3, kq = e & 7;
    wR[i] = *(const float4*)(W + (size_t)(n0+wr)*H + kq*4);
  }

  for (int it = 0; it < 16; it++) {
#pragma unroll
    for (int i = 0; i < 4; i++) {
      int e = tid + i*256; int row = e >> 3, kq = e & 7;
      Ash[kq*4+0][row] = aR[i].x; Ash[kq*4+1][row] = aR[i].y;
      Ash[kq*4+2][row] = aR[i].z; Ash[kq*4+3][row] = aR[i].w;
    }
#pragma unroll
    for (int i = 0; i < 2; i++) {
      int e = tid + i*256; int wr = e >> 3, kq = e & 7;
      Wsh[kq*4+0][wr] = wR[i].x; Wsh[kq*4+1][wr] = wR[i].y;
      Wsh[kq*4+2][wr] = wR[i].z; Wsh[kq*4+3][wr] = wR[i].w;
    }
    __syncthreads();
    if (it < 15) {
      int kt = (it+1) * 32;
#pragma unroll
      for (int i = 0; i < 4; i++) {
        int e = tid + i*256; int row = e >> 3, kq = e & 7;
        aR[i] = *(const float4*)(A + row*512 + kt + kq*4);
      }
#pragma unroll
      for (int i = 0; i < 2; i++) {
        int e = tid + i*256; int wr = e >> 3, kq = e & 7;
        wR[i] = *(const float4*)(W + (size_t)(n0+wr)*H + kt + kq*4);
      }
    }
#pragma unroll
    for (int kk = 0; kk < 32; kk++) {
      ulonglong2 a01 = *(const ulonglong2*)&Ash[kk][r0];
      ulonglong2 a23 = *(const ulonglong2*)&Ash[kk][r0 + 4];
      float4 ww = *(const float4*)&Wsh[kk][c0];
      unsigned long long w0, w1, w2, w3;
      PACK2(w0, ww.x); PACK2(w1, ww.y); PACK2(w2, ww.z); PACK2(w3, ww.w);
      FFMA2(acc[0][0], a01.x, w0); FFMA2(acc[0][1], a01.x, w1);
      FFMA2(acc[0][2], a01.x, w2); FFMA2(acc[0][3], a01.x, w3);
      FFMA2(acc[1][0], a01.y, w0); FFMA2(acc[1][1], a01.y, w1);
      FFMA2(acc[1][2], a01.y, w2); FFMA2(acc[1][3], a01.y, w3);
      FFMA2(acc[2][0], a23.x, w0); FFMA2(acc[2][1], a23.x, w1);
      FFMA2(acc[2][2], a23.x, w2); FFMA2(acc[2][3], a23.x, w3);
      FFMA2(acc[3][0], a23.y, w0); FFMA2(acc[3][1], a23.y, w1);
      FFMA2(acc[3][2], a23.y, w2); FFMA2(acc[3][3], a23.y, w3);
    }
    __syncthreads();
  }
  float t = *tptr;
  const float* gb = d_g + (size_t)s*BV;
#pragma unroll
  for (int p = 0; p < 4; p++) {
    int ra = r0 + 2*p, rb = ra + 1;
#pragma unroll
    for (int c = 0; c < 4; c++) {
      int col = n0 + c0 + c;
      U64F2 u; u.u = acc[p][c];
      float bv = bias[col];
      d_logits[(size_t)ra*V + col] = (u.f.x + bv + gb[(size_t)ra*V + col]) / t;
      d_logits[(size_t)rb*V + col] = (u.f.y + bv + gb[(size_t)rb*V + col]) / t;
    }
  }
}

// ---------------- per-step: GRU combine + cosine gate + bn3 ------------------
__global__ void k_gru(int s, const float* __restrict__ g3, const float* __restrict__ b3) {
  __shared__ float sh[128];
  int b = threadIdx.x, c0 = blockIdx.x * 4;
  const float* gim = d_gim + s*H3;
  float hx2[4], hm2[4];
#pragma unroll
  for (int j = 0; j < 4; j++) {
    int col = c0 + j;
    float ir = d_gi [b*H3+col], iz = d_gi [b*H3+H+col], in_ = d_gi [b*H3+2*H+col];
    float hr = d_ghx[b*H3+col], hz = d_ghx[b*H3+H+col], hn  = d_ghx[b*H3+2*H+col];
    float h  = d_hx[b*H+col];
    float r  = sig(ir+hr), zg = sig(iz+hz);
    float n  = tanhf(in_ + r*hn);
    hx2[j] = (1.f-zg)*n + zg*h;
    float mir = gim[col], miz = gim[H+col], min_ = gim[2*H+col];
    float mhr = d_ghm[b*H3+col], mhz = d_ghm[b*H3+H+col], mhn = d_ghm[b*H3+2*H+col];
    float hmv = d_hm[b*H+col];
    float rm  = sig(mir+mhr), zm = sig(miz+mhz);
    float nm  = tanhf(min_ + rm*mhn);
    hm2[j] = (1.f-zm)*nm + zm*hmv;
    d_hx[b*H+col] = hx2[j];
    d_hm[b*H+col] = hm2[j];
  }
  float dot=0.f, na=0.f, nb=0.f;
#pragma unroll
  for (int j = 0; j < 4; j++) { dot += hx2[j]*hm2[j]; na += hx2[j]*hx2[j]; nb += hm2[j]*hm2[j]; }
  float gate = dot / fmaxf(sqrtf(na)*sqrtf(nb), EPS_COS);
#pragma unroll
  for (int j = 0; j < 4; j++) {
    int col = c0 + j;
    float o   = leaky(gate*hx2[j] + (1.f-gate)*hm2[j]);
    float mu  = bredsum(o, sh) * (1.f/B);
    float dd  = o - mu;
    float var = bredsum(dd*dd, sh) * (1.f/B);
    d_o[b*H+col] = g3[col]*dd*rsqrtf(var + EPS_BN) + b3[col];
  }
}

// ---------------- per-step: softmax + argmax + write probs -------------------
__global__ void __launch_bounds__(512) k_smax(int s, float* __restrict__ out) {
  __shared__ float se[V];
  __shared__ float sh[512];
  __shared__ int   shi[512];
  int b = blockIdx.x, t = threadIdx.x;
  const float* row = d_logits + (size_t)b*V;
  float m = -3.0e38f;
  for (int v = t; v < V; v += 512) m = fmaxf(m, row[v]);
  sh[t] = m; __syncthreads();
#pragma unroll
  for (int o = 256; o > 0; o >>= 1) { if (t < o) sh[t] = fmaxf(sh[t], sh[t+o]); __syncthreads(); }
  m = sh[0]; __syncthreads();
  float sum = 0.f;
  for (int v = t; v < V; v += 512) { float e = expf(row[v]-m); se[v] = e; sum += e; }
  sh[t] = sum; __syncthreads();
#pragma unroll
  for (int o = 256; o > 0; o >>= 1) { if (t < o) sh[t] += sh[t+o]; __syncthreads(); }
  sum = sh[0]; __syncthreads();
  float best = -1.f; int bi = 0;
  float* orow = out + (size_t)b*S*V + (size_t)s*V;
  for (int v = t; v < V; v += 512) {
    float p = se[v] / sum;
    orow[v] = p;
    if (p > best) { best = p; bi = v; }
  }
  sh[t] = best; shi[t] = bi; __syncthreads();
#pragma unroll
  for (int o = 256; o > 0; o >>= 1) {
    if (t < o) {
      float ov = sh[t+o]; int oi = shi[t+o];
      if (ov > sh[t] || (ov == sh[t] && oi < shi[t])) { sh[t] = ov; shi[t] = oi; }
    }
    __syncthreads();
  }
  if (t == 0) d_prev[b] = shi[0];
}

// ---------------- launch ------------------------------------------------------
extern "C" void kernel_launch(void* const* d_in, const int* in_sizes, int n_in,
                              void* d_out, int out_size) {
  const float* z      = (const float*)d_in[0];
  const float* temp   = (const float*)d_in[1];
  const float* z2h_w  = (const float*)d_in[2];
  const float* z2h_b  = (const float*)d_in[3];
  const float* bn1_g  = (const float*)d_in[4];
  const float* bn1_b  = (const float*)d_in[5];
  const float* emb    = (const float*)d_in[6];
  const float* bn2_g  = (const float*)d_in[7];
  const float* bn2_b  = (const float*)d_in[8];
  const float* memory = (const float*)d_in[9];
  const float* gx_wih = (const float*)d_in[10];
  const float* gx_whh = (const float*)d_in[11];
  const float* gx_bih = (const float*)d_in[12];
  const float* gx_bhh = (const float*)d_in[13];
  const float* gm_wih = (const float*)d_in[14];
  const float* gm_whh = (const float*)d_in[15];
  const float* gm_bih = (const float*)d_in[16];
  const float* gm_bhh = (const float*)d_in[17];
  const float* bn3_g  = (const float*)d_in[18];
  const float* bn3_b  = (const float*)d_in[19];
  const float* h2o_w  = (const float*)d_in[20];
  const float* h2o_b  = (const float*)d_in[21];
  float* out = (float*)d_out;

  // reordered so k_gumbel sits where ncu's -s/-c window previously captured
  // k_prep (4th launch) -> next profile should report k_gumbel's duration.
  k_keys  <<<1, 64>>>();
  k_z0    <<<128, 128>>>(z, z2h_w, z2h_b, bn1_g, bn1_b);
  k_prep  <<<256, 256>>>();
  k_gumbel<<<(S*(size_t)BV)/256, 256>>>();
  k_siz   <<<128, 128>>>(bn2_g, bn2_b);
  k_cz    <<<48, 256>>>(gx_wih, gx_bih);
  k_gim   <<<S, 256>>>(memory, gm_wih, gm_bih);

  for (int s = 0; s < S; s++) {
    k_embbn <<<128, 128>>>(emb, bn2_g, bn2_b);
    k_gemm3 <<<dim3(48,1,3), 256>>>(gx_wih, gx_whh, gm_whh, gx_bhh, gm_bhh);
    k_gru   <<<128, 128>>>(s, bn3_g, bn3_b);
    k_logits<<<128, 256>>>(s, h2o_w, h2o_b, temp);
    k_smax  <<<128, 512>>>(s, out);
  }
}

// round 16
// speedup vs baseline: 1.1076x; 1.0430x over previous
#include <cuda_runtime.h>
#include <math.h>

#define B   128
#define NZ  128
#define H   512
#define V   8192
#define S   64
#define H3  1536
#define EPS_BN  1e-5f
#define EPS_COS 1e-8f
#define NEG 0.2f
#define BV  (B*V)

// ---------------- static device scratch (allocations forbidden) ------------
__device__ __align__(16) float d_z0 [B*H];
__device__ __align__(16) float d_siz[B*H];
__device__ __align__(16) float d_cz [B*H3];
__device__ __align__(16) float d_gim[S*H3];
__device__ float d_g[(size_t)S*BV];           // 256 MiB gumbel noise
__device__ __align__(16) float d_six[B*H];
__device__ __align__(16) float d_gi [B*H3];
__device__ __align__(16) float d_ghx[B*H3];
__device__ __align__(16) float d_ghm[B*H3];
__device__ __align__(16) float d_hx [B*H];
__device__ __align__(16) float d_hm [B*H];
__device__ __align__(16) float d_o  [B*H];
__device__ float d_logits[B*V];
__device__ int   d_prev[B];
__device__ unsigned d_keys[2*S];

// ---------------- threefry2x32 (bit-exact vs JAX) --------------------------
__device__ __forceinline__ void threefry(unsigned k0, unsigned k1,
                                         unsigned c0, unsigned c1,
                                         unsigned &o0, unsigned &o1) {
  unsigned ks2 = k0 ^ k1 ^ 0x1BD11BDAu;
  unsigned x0 = c0 + k0, x1 = c1 + k1;
#define TFR(r) { x0 += x1; x1 = __funnelshift_l(x1, x1, (r)); x1 ^= x0; }
  TFR(13) TFR(15) TFR(26) TFR(6)   x0 += k1;  x1 += ks2 + 1u;
  TFR(17) TFR(29) TFR(16) TFR(24)  x0 += ks2; x1 += k0 + 2u;
  TFR(13) TFR(15) TFR(26) TFR(6)   x0 += k0;  x1 += k1 + 3u;
  TFR(17) TFR(29) TFR(16) TFR(24)  x0 += k1;  x1 += ks2 + 4u;
  TFR(13) TFR(15) TFR(26) TFR(6)   x0 += ks2; x1 += k0 + 5u;
#undef TFR
  o0 = x0; o1 = x1;
}

// full-precision ln via atanh-form polynomial (~1-2 ulp), u in (0, 1)
__device__ __forceinline__ float fast_ln(float u) {
  int ix = __float_as_int(u);
  int e  = (ix - 0x3f3504f3) >> 23;              // split at sqrt(0.5)
  float m = __int_as_float(ix - (e << 23));      // m in [0.7071, 1.4142)
  float s = m - 1.0f;
  float d = 2.0f + s;
  float rd; asm("rcp.approx.f32 %0, %1;" : "=f"(rd) : "f"(d));
  float t  = s * rd;                             // atanh argument
  float t2 = t * t;
  float w  = fmaf(fmaf(fmaf(0.14285714f, t2, 0.2f), t2, 0.33333334f), t2, 1.0f);
  float fe = (float)e;
  float lo = fmaf(2.0f * t, w, fe * 1.4286068e-6f);
  return fmaf(fe, 0.69314575f, lo);              // ln2 hi/lo split
}

__device__ __forceinline__ float gumbel_from_bits(unsigned bits) {
  float f = __uint_as_float((bits >> 9) | 0x3f800000u) - 1.0f;   // [0,1)
  float u = fmaxf(1e-6f, __fadd_rn(__fmul_rn(f, (1.0f - 1e-6f) - 1e-6f), 1e-6f));
  float x = -fast_ln(u);                         // in [1.1e-6, 13.9]
  float lx; asm("lg2.approx.f32 %0, %1;" : "=f"(lx) : "f"(x));
  return -0.69314718f * lx;                      // -ln(x)
}

__global__ void k_keys() {
  int s = threadIdx.x;
  if (s < S) { unsigned o0,o1; threefry(0u,42u,0u,(unsigned)s,o0,o1);
               d_keys[2*s]=o0; d_keys[2*s+1]=o1; }
}

// Partitionable threefry random_bits: counter (0, i), 32-bit out = o0 ^ o1.
__global__ void k_gumbel() {
  int idx = blockIdx.x * blockDim.x + threadIdx.x;
  int s = idx / BV;
  int i = idx - s * BV;
  unsigned o0,o1;
  threefry(d_keys[2*s], d_keys[2*s+1], 0u, (unsigned)i, o0, o1);
  d_g[(size_t)s * BV + i] = gumbel_from_bits(o0 ^ o1);
}

// ---------------- helpers ---------------------------------------------------
__device__ __forceinline__ float bredsum(float v, float* sh) {
  int t = threadIdx.x;
  sh[t] = v; __syncthreads();
#pragma unroll
  for (int o = 64; o > 0; o >>= 1) { if (t < o) sh[t] += sh[t+o]; __syncthreads(); }
  float r = sh[0]; __syncthreads();
  return r;
}
__device__ __forceinline__ float leaky(float x) { return x >= 0.f ? x : NEG*x; }
__device__ __forceinline__ float sig(float x)   { return 1.f/(1.f+expf(-x)); }

#define FFMA2(acc, a, b) \
  asm("fma.rn.f32x2 %0, %1, %2, %0;" : "+l"(acc) : "l"(a), "l"(b))
#define PACK2(out, x) \
  asm("mov.b64 %0, {%1, %1};" : "=l"(out) : "r"(__float_as_uint(x)))

union U64F2 { unsigned long long u; float2 f; };

// ---------------- setup kernels ---------------------------------------------
__global__ void k_z0(const float* __restrict__ z, const float* __restrict__ w,
                     const float* __restrict__ bias, const float* __restrict__ gg,
                     const float* __restrict__ bb) {
  __shared__ float sh[128];
  int b = threadIdx.x, c0 = blockIdx.x * 4;
  const float* zr = z + b*NZ;
  for (int j = 0; j < 4; j++) {
    int col = c0 + j;
    float acc = bias[col];
    const float* wr = w + col*NZ;
    for (int k = 0; k < NZ; k++) acc = fmaf(zr[k], wr[k], acc);
    float v   = leaky(acc);
    float mu  = bredsum(v, sh) * (1.f/B);
    float dd  = v - mu;
    float var = bredsum(dd*dd, sh) * (1.f/B);
    d_z0[b*H + col] = gg[col]*dd*rsqrtf(var + EPS_BN) + bb[col];
  }
}

__global__ void k_prep() {
  int i = blockIdx.x * blockDim.x + threadIdx.x;
  if (i < B*H) { float v = d_z0[i]; d_hx[i] = v; d_hm[i] = v; }
  if (i < B) d_prev[i] = V - 1;
}

__global__ void k_siz(const float* __restrict__ g2, const float* __restrict__ b2) {
  __shared__ float sh[128];
  int b = threadIdx.x, c0 = blockIdx.x * 4;
  for (int j = 0; j < 4; j++) {
    int col = c0 + j;
    float v   = d_z0[b*H + col];
    float mu  = bredsum(v, sh) * (1.f/B);
    float dd  = v - mu;
    float var = bredsum(dd*dd, sh) * (1.f/B);
    d_siz[b*H + col] = g2[H+col]*dd*rsqrtf(var + EPS_BN) + b2[H+col];
  }
}

__global__ void k_gim(const float* __restrict__ mem, const float* __restrict__ W,
                      const float* __restrict__ bias) {
  __shared__ float a[2*H];
  int s = blockIdx.x;
  for (int k = threadIdx.x; k < 2*H; k += 256) a[k] = mem[(size_t)s*2*H + k];
  __syncthreads();
  for (int n = threadIdx.x; n < H3; n += 256) {
    float acc = bias[n];
    const float* w = W + (size_t)n*2*H;
    for (int k = 0; k < 2*H; k++) acc = fmaf(a[k], w[k], acc);
    d_gim[s*H3 + n] = acc;
  }
}

__global__ void k_embbn(const float* __restrict__ emb,
                        const float* __restrict__ g2, const float* __restrict__ b2) {
  __shared__ float sh[128];
  int b = threadIdx.x, c0 = blockIdx.x * 4;
  const float* er = emb + (size_t)d_prev[b]*H;
  for (int j = 0; j < 4; j++) {
    int col = c0 + j;
    float e   = leaky(er[col]);
    float mu  = bredsum(e, sh) * (1.f/B);
    float dd  = e - mu;
    float var = bredsum(dd*dd, sh) * (1.f/B);
    d_six[b*H + col] = g2[col]*dd*rsqrtf(var + EPS_BN) + b2[col];
  }
}

// ---------------- tiled fp32 GEMM core (R7), K-chunk 32 + prefetch ----------
template <int RPT>
__device__ __forceinline__ void gemm_core(
    const float* __restrict__ A, const float* __restrict__ W, int ldw,
    const float* __restrict__ bias, const float* __restrict__ addM, int ldadd,
    float* __restrict__ C, int ldc, int n0,
    const float* __restrict__ gbase, float t) {
  constexpr int NT = 8 * RPT;
  constexpr int TX = NT / 4;
  constexpr int WF = (NT * 8) / 256;
  __shared__ __align__(16) float Ash[32][132];
  __shared__ __align__(16) float Wsh[32][NT + 4];
  int tid = threadIdx.x;
  int tx = tid % TX, ty = tid / TX;
  int r0 = ty * RPT, c0 = tx * 4;
  float acc[RPT][4];
#pragma unroll
  for (int j = 0; j < RPT; j++)
#pragma unroll
    for (int c = 0; c < 4; c++) acc[j][c] = 0.f;

  float4 aR[4], wR[WF];
#pragma unroll
  for (int i = 0; i < 4; i++) {
    int e = tid + i*256; int row = e >> 3, kq = e & 7;
    aR[i] = *(const float4*)(A + row*512 + kq*4);
  }
#pragma unroll
  for (int i = 0; i < WF; i++) {
    int e = tid + i*256; int wr = e >> 3, kq = e & 7;
    wR[i] = *(const float4*)(W + (size_t)(n0+wr)*ldw + kq*4);
  }

  for (int it = 0; it < 16; it++) {
#pragma unroll
    for (int i = 0; i < 4; i++) {
      int e = tid + i*256; int row = e >> 3, kq = e & 7;
      Ash[kq*4+0][row] = aR[i].x; Ash[kq*4+1][row] = aR[i].y;
      Ash[kq*4+2][row] = aR[i].z; Ash[kq*4+3][row] = aR[i].w;
    }
#pragma unroll
    for (int i = 0; i < WF; i++) {
      int e = tid + i*256; int wr = e >> 3, kq = e & 7;
      Wsh[kq*4+0][wr] = wR[i].x; Wsh[kq*4+1][wr] = wR[i].y;
      Wsh[kq*4+2][wr] = wR[i].z; Wsh[kq*4+3][wr] = wR[i].w;
    }
    __syncthreads();
    if (it < 15) {
      int kt = (it+1) * 32;
#pragma unroll
      for (int i = 0; i < 4; i++) {
        int e = tid + i*256; int row = e >> 3, kq = e & 7;
        aR[i] = *(const float4*)(A + row*512 + kt + kq*4);
      }
#pragma unroll
      for (int i = 0; i < WF; i++) {
        int e = tid + i*256; int wr = e >> 3, kq = e & 7;
        wR[i] = *(const float4*)(W + (size_t)(n0+wr)*ldw + kt + kq*4);
      }
    }
#pragma unroll
    for (int kk = 0; kk < 32; kk++) {
      float av[RPT];
#pragma unroll
      for (int q = 0; q < RPT/4; q++) {
        float4 aa = *(const float4*)&Ash[kk][r0 + q*4];
        av[q*4+0]=aa.x; av[q*4+1]=aa.y; av[q*4+2]=aa.z; av[q*4+3]=aa.w;
      }
      float4 ww = *(const float4*)&Wsh[kk][c0];
      float wv4[4] = {ww.x, ww.y, ww.z, ww.w};
#pragma unroll
      for (int j = 0; j < RPT; j++)
#pragma unroll
        for (int c = 0; c < 4; c++)
          acc[j][c] = fmaf(av[j], wv4[c], acc[j][c]);
    }
    __syncthreads();
  }
#pragma unroll
  for (int j = 0; j < RPT; j++) {
    int row = r0 + j;
#pragma unroll
    for (int c = 0; c < 4; c++) {
      int col = n0 + c0 + c;
      float v = acc[j][c];
      if (bias)  v += bias[col];
      if (addM)  v += addM[(size_t)row*ldadd + col];
      if (gbase) v = (v + gbase[(size_t)row*V + col]) / t;
      C[(size_t)row*ldc + col] = v;
    }
  }
}

__global__ void __launch_bounds__(256) k_cz(const float* __restrict__ W,
                                            const float* __restrict__ bias) {
  gemm_core<4>(d_siz, W + H, 2*H, bias, (const float*)0, 0,
               d_cz, H3, blockIdx.x*32, (const float*)0, 1.f);
}

__global__ void __launch_bounds__(256) k_gemm3(
    const float* __restrict__ wih_x, const float* __restrict__ whh_x,
    const float* __restrict__ whh_m, const float* __restrict__ bhh_x,
    const float* __restrict__ bhh_m) {
  int n0 = blockIdx.x * 32;
  int z = blockIdx.z;
  const float* A    = (z==0) ? d_six : (z==1) ? d_hx : d_hm;
  const float* W    = (z==0) ? wih_x : (z==1) ? whh_x : whh_m;
  int ldw           = (z==0) ? 2*H : H;
  const float* bias = (z==0) ? (const float*)0 : (z==1) ? bhh_x : bhh_m;
  const float* addM = (z==0) ? d_cz : (const float*)0;
  float* Cm         = (z==0) ? d_gi : (z==1) ? d_ghx : d_ghm;
  gemm_core<4>(A, W, ldw, bias, addM, H3, Cm, H3, n0, (const float*)0, 1.f);
}

// ---------------- FFMA2 logits GEMM (R14 best) --------------------------------
__global__ void __launch_bounds__(256) k_logits(
    int s, const float* __restrict__ W, const float* __restrict__ bias,
    const float* __restrict__ tptr) {
  __shared__ __align__(16) float Ash[32][132];
  __shared__ __align__(16) float Wsh[32][68];
  int tid = threadIdx.x;
  int tx = tid & 15, ty = tid >> 4;
  int r0 = ty * 8, c0 = tx * 4;
  int n0 = blockIdx.x * 64;
  const float* A = d_o;

  unsigned long long acc[4][4];
#pragma unroll
  for (int p = 0; p < 4; p++)
#pragma unroll
    for (int c = 0; c < 4; c++) acc[p][c] = 0ull;

  float4 aR[4], wR[2];
#pragma unroll
  for (int i = 0; i < 4; i++) {
    int e = tid + i*256; int row = e >> 3, kq = e & 7;
    aR[i] = *(const float4*)(A + row*512 + kq*4);
  }
#pragma unroll
  for (int i = 0; i < 2; i++) {
    int e = tid + i*256; int wr = e >> 3, kq = e & 7;
    wR[i] = *(const float4*)(W + (size_t)(n0+wr)*H + kq*4);
  }

  for (int it = 0; it < 16; it++) {
#pragma unroll
    for (int i = 0; i < 4; i++) {
      int e = tid + i*256; int row = e >> 3, kq = e & 7;
      Ash[kq*4+0][row] = aR[i].x; Ash[kq*4+1][row] = aR[i].y;
      Ash[kq*4+2][row] = aR[i].z; Ash[kq*4+3][row] = aR[i].w;
    }
#pragma unroll
    for (int i = 0; i < 2; i++) {
      int e = tid + i*256; int wr = e >> 3, kq = e & 7;
      Wsh[kq*4+0][wr] = wR[i].x; Wsh[kq*4+1][wr] = wR[i].y;
      Wsh[kq*4+2][wr] = wR[i].z; Wsh[kq*4+3][wr] = wR[i].w;
    }
    __syncthreads();
    if (it < 15) {
      int kt = (it+1) * 32;
#pragma unroll
      for (int i = 0; i < 4; i++) {
        int e = tid + i*256; int row = e >> 3, kq = e & 7;
        aR[i] = *(const float4*)(A + row*512 + kt + kq*4);
      }
#pragma unroll
      for (int i = 0; i < 2; i++) {
        int e = tid + i*256; int wr = e >> 3, kq = e & 7;
        wR[i] = *(const float4*)(W + (size_t)(n0+wr)*H + kt + kq*4);
      }
    }
#pragma unroll
    for (int kk = 0; kk < 32; kk++) {
      ulonglong2 a01 = *(const ulonglong2*)&Ash[kk][r0];
      ulonglong2 a23 = *(const ulonglong2*)&Ash[kk][r0 + 4];
      float4 ww = *(const float4*)&Wsh[kk][c0];
      unsigned long long w0, w1, w2, w3;
      PACK2(w0, ww.x); PACK2(w1, ww.y); PACK2(w2, ww.z); PACK2(w3, ww.w);
      FFMA2(acc[0][0], a01.x, w0); FFMA2(acc[0][1], a01.x, w1);
      FFMA2(acc[0][2], a01.x, w2); FFMA2(acc[0][3], a01.x, w3);
      FFMA2(acc[1][0], a01.y, w0); FFMA2(acc[1][1], a01.y, w1);
      FFMA2(acc[1][2], a01.y, w2); FFMA2(acc[1][3], a01.y, w3);
      FFMA2(acc[2][0], a23.x, w0); FFMA2(acc[2][1], a23.x, w1);
      FFMA2(acc[2][2], a23.x, w2); FFMA2(acc[2][3], a23.x, w3);
      FFMA2(acc[3][0], a23.y, w0); FFMA2(acc[3][1], a23.y, w1);
      FFMA2(acc[3][2], a23.y, w2); FFMA2(acc[3][3], a23.y, w3);
    }
    __syncthreads();
  }
  float t = *tptr;
  const float* gb = d_g + (size_t)s*BV;
#pragma unroll
  for (int p = 0; p < 4; p++) {
    int ra = r0 + 2*p, rb = ra + 1;
#pragma unroll
    for (int c = 0; c < 4; c++) {
      int col = n0 + c0 + c;
      U64F2 u; u.u = acc[p][c];
      float bv = bias[col];
      d_logits[(size_t)ra*V + col] = (u.f.x + bv + gb[(size_t)ra*V + col]) / t;
      d_logits[(size_t)rb*V + col] = (u.f.y + bv + gb[(size_t)rb*V + col]) / t;
    }
  }
}

// ---------------- per-step: GRU combine + cosine gate + bn3 ------------------
__global__ void k_gru(int s, const float* __restrict__ g3, const float* __restrict__ b3) {
  __shared__ float sh[128];
  int b = threadIdx.x, c0 = blockIdx.x * 4;
  const float* gim = d_gim + s*H3;
  float hx2[4], hm2[4];
#pragma unroll
  for (int j = 0; j < 4; j++) {
    int col = c0 + j;
    float ir = d_gi [b*H3+col], iz = d_gi [b*H3+H+col], in_ = d_gi [b*H3+2*H+col];
    float hr = d_ghx[b*H3+col], hz = d_ghx[b*H3+H+col], hn  = d_ghx[b*H3+2*H+col];
    float h  = d_hx[b*H+col];
    float r  = sig(ir+hr), zg = sig(iz+hz);
    float n  = tanhf(in_ + r*hn);
    hx2[j] = (1.f-zg)*n + zg*h;
    float mir = gim[col], miz = gim[H+col], min_ = gim[2*H+col];
    float mhr = d_ghm[b*H3+col], mhz = d_ghm[b*H3+H+col], mhn = d_ghm[b*H3+2*H+col];
    float hmv = d_hm[b*H+col];
    float rm  = sig(mir+mhr), zm = sig(miz+mhz);
    float nm  = tanhf(min_ + rm*mhn);
    hm2[j] = (1.f-zm)*nm + zm*hmv;
    d_hx[b*H+col] = hx2[j];
    d_hm[b*H+col] = hm2[j];
  }
  float dot=0.f, na=0.f, nb=0.f;
#pragma unroll
  for (int j = 0; j < 4; j++) { dot += hx2[j]*hm2[j]; na += hx2[j]*hx2[j]; nb += hm2[j]*hm2[j]; }
  float gate = dot / fmaxf(sqrtf(na)*sqrtf(nb), EPS_COS);
#pragma unroll
  for (int j = 0; j < 4; j++) {
    int col = c0 + j;
    float o   = leaky(gate*hx2[j] + (1.f-gate)*hm2[j]);
    float mu  = bredsum(o, sh) * (1.f/B);
    float dd  = o - mu;
    float var = bredsum(dd*dd, sh) * (1.f/B);
    d_o[b*H+col] = g3[col]*dd*rsqrtf(var + EPS_BN) + b3[col];
  }
}

// ---------------- per-step: softmax + argmax + write probs (float4) ----------
__global__ void __launch_bounds__(512) k_smax(int s, float* __restrict__ out) {
  __shared__ __align__(16) float se[V];
  __shared__ float sh[512];
  __shared__ int   shi[512];
  int b = blockIdx.x, t = threadIdx.x;
  const float4* row4 = (const float4*)(d_logits + (size_t)b*V);
  float m = -3.0e38f;
#pragma unroll
  for (int i = 0; i < 4; i++) {
    float4 x = row4[t + i*512];
    m = fmaxf(m, fmaxf(fmaxf(x.x, x.y), fmaxf(x.z, x.w)));
  }
  sh[t] = m; __syncthreads();
#pragma unroll
  for (int o = 256; o > 0; o >>= 1) { if (t < o) sh[t] = fmaxf(sh[t], sh[t+o]); __syncthreads(); }
  m = sh[0]; __syncthreads();
  float sum = 0.f;
#pragma unroll
  for (int i = 0; i < 4; i++) {
    int v4 = t + i*512;
    float4 x = row4[v4];
    float4 e;
    e.x = expf(x.x - m); e.y = expf(x.y - m);
    e.z = expf(x.z - m); e.w = expf(x.w - m);
    ((float4*)se)[v4] = e;
    sum += e.x; sum += e.y; sum += e.z; sum += e.w;
  }
  sh[t] = sum; __syncthreads();
#pragma unroll
  for (int o = 256; o > 0; o >>= 1) { if (t < o) sh[t] += sh[t+o]; __syncthreads(); }
  sum = sh[0]; __syncthreads();
  float rs = 1.0f / sum;
  float best = -1.f; int bi = 0;
  float4* orow4 = (float4*)(out + (size_t)b*S*V + (size_t)s*V);
#pragma unroll
  for (int i = 0; i < 4; i++) {
    int v4 = t + i*512;
    float4 e = ((const float4*)se)[v4];
    float4 p;
    p.x = e.x*rs; p.y = e.y*rs; p.z = e.z*rs; p.w = e.w*rs;
    orow4[v4] = p;
    int vb = v4 * 4;
    if (p.x > best) { best = p.x; bi = vb;     }
    if (p.y > best) { best = p.y; bi = vb + 1; }
    if (p.z > best) { best = p.z; bi = vb + 2; }
    if (p.w > best) { best = p.w; bi = vb + 3; }
  }
  sh[t] = best; shi[t] = bi; __syncthreads();
#pragma unroll
  for (int o = 256; o > 0; o >>= 1) {
    if (t < o) {
      float ov = sh[t+o]; int oi = shi[t+o];
      if (ov > sh[t] || (ov == sh[t] && oi < shi[t])) { sh[t] = ov; shi[t] = oi; }
    }
    __syncthreads();
  }
  if (t == 0) d_prev[b] = shi[0];
}

// ---------------- launch ------------------------------------------------------
extern "C" void kernel_launch(void* const* d_in, const int* in_sizes, int n_in,
                              void* d_out, int out_size) {
  const float* z      = (const float*)d_in[0];
  const float* temp   = (const float*)d_in[1];
  const float* z2h_w  = (const float*)d_in[2];
  const float* z2h_b  = (const float*)d_in[3];
  const float* bn1_g  = (const float*)d_in[4];
  const float* bn1_b  = (const float*)d_in[5];
  const float* emb    = (const float*)d_in[6];
  const float* bn2_g  = (const float*)d_in[7];
  const float* bn2_b  = (const float*)d_in[8];
  const float* memory = (const float*)d_in[9];
  const float* gx_wih = (const float*)d_in[10];
  const float* gx_whh = (const float*)d_in[11];
  const float* gx_bih = (const float*)d_in[12];
  const float* gx_bhh = (const float*)d_in[13];
  const float* gm_wih = (const float*)d_in[14];
  const float* gm_whh = (const float*)d_in[15];
  const float* gm_bih = (const float*)d_in[16];
  const float* gm_bhh = (const float*)d_in[17];
  const float* bn3_g  = (const float*)d_in[18];
  const float* bn3_b  = (const float*)d_in[19];
  const float* h2o_w  = (const float*)d_in[20];
  const float* h2o_b  = (const float*)d_in[21];
  float* out = (float*)d_out;

  k_keys  <<<1, 64>>>();
  k_z0    <<<128, 128>>>(z, z2h_w, z2h_b, bn1_g, bn1_b);
  k_prep  <<<256, 256>>>();
  // INSTRUMENTATION: dummy k_logits in the ncu capture slot (4th launch).
  // Reads stale d_o; d_logits is fully overwritten by the real s=0 k_logits
  // before k_smax runs -> final output deterministic and unchanged.
  k_logits<<<128, 256>>>(0, h2o_w, h2o_b, temp);
  k_gumbel<<<(S*(size_t)BV)/256, 256>>>();
  k_siz   <<<128, 128>>>(bn2_g, bn2_b);
  k_cz    <<<48, 256>>>(gx_wih, gx_bih);
  k_gim   <<<S, 256>>>(memory, gm_wih, gm_bih);

  for (int s = 0; s < S; s++) {
    k_embbn <<<128, 128>>>(emb, bn2_g, bn2_b);
    k_gemm3 <<<dim3(48,1,3), 256>>>(gx_wih, gx_whh, gm_whh, gx_bhh, gm_bhh);
    k_gru   <<<128, 128>>>(s, bn3_g, bn3_b);
    k_logits<<<128, 256>>>(s, h2o_w, h2o_b, temp);
    k_smax  <<<128, 512>>>(s, out);
  }
}